// round 2
// baseline (speedup 1.0000x reference)
#include <cuda_runtime.h>

// ===========================================================================
// GCN: 3 layers, pull-based CSR aggregation, no float atomics.
//   out_i = leakyrelu( dinv_i * ( sum_{e: dst=i} g[src_e] + g[i] ) + b )
//   with g = (h @ W) * dinv  (row-scaled in GEMM epilogue)
// Algebraically identical to D^-1/2 (A+I) D^-1/2 (hW) + b.
//
// edge_index dtype is detected on-device (JAX may silently emit int32
// despite the reference saying int64).
// ===========================================================================

#define NMAX 100000
#define EMAX 1600000

__device__ int   g_is64;
__device__ int   g_deg[NMAX];
__device__ float g_dinv[NMAX];
__device__ int   g_offs[NMAX + 1];
__device__ int   g_cur[NMAX];
__device__ int   g_csrc[EMAX];
__device__ float g_G[(size_t)NMAX * 64];

// ---------------------------------------------------------------- dtype probe
// If the buffer is int64 (values < 2^31), the high 32-bit word of every entry
// is 0. If it is int32, "high words" are random node ids — all-zero over 64
// entries is impossible.
__global__ void k_detect(const unsigned int* __restrict__ w) {
    if (threadIdx.x == 0) {
        int ok = 1;
        #pragma unroll
        for (int i = 0; i < 64; i++) ok &= (w[2 * i + 1] == 0u);
        g_is64 = ok;
    }
}

__device__ __forceinline__ int load_idx(const void* ei, size_t pos, int is64) {
    if (is64) return (int)((const long long*)ei)[pos];
    return ((const int*)ei)[pos];
}

// ---------------------------------------------------------------- build CSR
__global__ void k_zero(int N) {
    int i = blockIdx.x * blockDim.x + threadIdx.x;
    if (i < N) g_deg[i] = 0;
}

__global__ void k_count(const void* __restrict__ ei, int E, int N) {
    int e = blockIdx.x * blockDim.x + threadIdx.x;
    if (e < E) {
        int is64 = g_is64;
        int dst = load_idx(ei, (size_t)E + e, is64);
        if ((unsigned)dst < (unsigned)N) atomicAdd(&g_deg[dst], 1);
    }
}

// single-block exclusive scan of deg -> offs/cursor, plus dinv = rsqrt(deg+1)
__global__ void k_scan(int N) {
    __shared__ int ssum[1024];
    int t = threadIdx.x;
    int chunk = (N + 1023) >> 10;
    int s = t * chunk;
    int e = min(s + chunk, N);
    int sum = 0;
    for (int i = s; i < e; i++) sum += g_deg[i];
    ssum[t] = sum;
    __syncthreads();
    for (int off = 1; off < 1024; off <<= 1) {
        int v = (t >= off) ? ssum[t - off] : 0;
        __syncthreads();
        ssum[t] += v;
        __syncthreads();
    }
    int run = (t == 0) ? 0 : ssum[t - 1];
    for (int i = s; i < e; i++) {
        g_offs[i] = run;
        g_cur[i]  = run;
        int d = g_deg[i];
        run += d;
        g_dinv[i] = rsqrtf((float)(d + 1));  // +1 self loop
    }
    if (t == 1023) g_offs[N] = ssum[1023];
}

__global__ void k_fill(const void* __restrict__ ei, int E, int N) {
    int e = blockIdx.x * blockDim.x + threadIdx.x;
    if (e < E) {
        int is64 = g_is64;
        int dst = load_idx(ei, (size_t)E + e, is64);
        int src = load_idx(ei, (size_t)e, is64);
        if ((unsigned)dst < (unsigned)N) {
            int pos = atomicAdd(&g_cur[dst], 1);
            g_csrc[pos] = ((unsigned)src < (unsigned)N) ? src : 0;
        }
    }
}

// ---------------------------------------------------------------- GEMM
// g = (X @ W) * dinv[row]    X:[N,DIN] W:[DIN,DOUT] -> g_G:[N,DOUT]
// Each thread: 4 rows x 4 cols. W staged in shared.
template <int DIN, int DOUT>
__global__ void k_gemm(const float* __restrict__ X, const float* __restrict__ W, int N) {
    __shared__ float sW[DIN * DOUT];
    for (int i = threadIdx.x; i < DIN * DOUT; i += blockDim.x) sW[i] = W[i];
    __syncthreads();

    constexpr int CG  = DOUT / 4;     // col groups of 4
    constexpr int RPB = (256 / CG) * 4;
    int jg   = threadIdx.x % CG;
    int ig   = threadIdx.x / CG;
    int row0 = blockIdx.x * RPB + ig * 4;
    if (row0 >= N) return;

    if (row0 + 4 <= N) {
        float4 acc[4];
        #pragma unroll
        for (int r = 0; r < 4; r++) acc[r] = make_float4(0.f, 0.f, 0.f, 0.f);
        for (int k0 = 0; k0 < DIN; k0 += 4) {
            float4 xv[4];
            #pragma unroll
            for (int r = 0; r < 4; r++)
                xv[r] = *(const float4*)(X + (size_t)(row0 + r) * DIN + k0);
            #pragma unroll
            for (int kk = 0; kk < 4; kk++) {
                float4 w = *(const float4*)(sW + (k0 + kk) * DOUT + jg * 4);
                #pragma unroll
                for (int r = 0; r < 4; r++) {
                    float xs = (kk == 0) ? xv[r].x : (kk == 1) ? xv[r].y
                             : (kk == 2) ? xv[r].z : xv[r].w;
                    acc[r].x += xs * w.x;
                    acc[r].y += xs * w.y;
                    acc[r].z += xs * w.z;
                    acc[r].w += xs * w.w;
                }
            }
        }
        #pragma unroll
        for (int r = 0; r < 4; r++) {
            float sc = g_dinv[row0 + r];
            float4 o = make_float4(acc[r].x * sc, acc[r].y * sc,
                                   acc[r].z * sc, acc[r].w * sc);
            *(float4*)(g_G + (size_t)(row0 + r) * DOUT + jg * 4) = o;
        }
    } else {
        // tail rows: scalar
        for (int r = 0; r < 4; r++) {
            int row = row0 + r;
            if (row >= N) break;
            float a0 = 0.f, a1 = 0.f, a2 = 0.f, a3 = 0.f;
            for (int k = 0; k < DIN; k++) {
                float xs = X[(size_t)row * DIN + k];
                const float* w = sW + k * DOUT + jg * 4;
                a0 += xs * w[0]; a1 += xs * w[1]; a2 += xs * w[2]; a3 += xs * w[3];
            }
            float sc = g_dinv[row];
            float4 o = make_float4(a0 * sc, a1 * sc, a2 * sc, a3 * sc);
            *(float4*)(g_G + (size_t)row * DOUT + jg * 4) = o;
        }
    }
}

// ---------------------------------------------------------------- aggregate
// warp-per-node pull reduction. D=64: lane holds float2; D=32: lane holds float.
template <int D, bool RELU>
__global__ void k_agg(const float* __restrict__ bias, float* __restrict__ out, int N) {
    int gid  = blockIdx.x * blockDim.x + threadIdx.x;
    int node = gid >> 5;
    int lane = gid & 31;
    if (node >= N) return;  // warp-uniform

    const float* __restrict__ G = g_G;
    int beg = g_offs[node];
    int end = g_offs[node + 1];

    if (D == 64) {
        float2 acc = *(const float2*)(G + (size_t)node * 64 + lane * 2);  // self loop
        for (int e0 = beg; e0 < end; e0 += 32) {
            int idx = e0 + lane;
            int sl  = (idx < end) ? g_csrc[idx] : 0;
            int cnt = min(32, end - e0);
            #pragma unroll 4
            for (int j = 0; j < cnt; j++) {
                int s = __shfl_sync(0xffffffffu, sl, j);
                float2 v = *(const float2*)(G + (size_t)s * 64 + lane * 2);
                acc.x += v.x;
                acc.y += v.y;
            }
        }
        float  sc = g_dinv[node];
        float2 b  = *(const float2*)(bias + lane * 2);
        float ox = acc.x * sc + b.x;
        float oy = acc.y * sc + b.y;
        if (RELU) {
            ox = (ox >= 0.f) ? ox : 0.01f * ox;
            oy = (oy >= 0.f) ? oy : 0.01f * oy;
        }
        *(float2*)(out + (size_t)node * 64 + lane * 2) = make_float2(ox, oy);
    } else {  // D == 32
        float acc = G[(size_t)node * 32 + lane];
        for (int e0 = beg; e0 < end; e0 += 32) {
            int idx = e0 + lane;
            int sl  = (idx < end) ? g_csrc[idx] : 0;
            int cnt = min(32, end - e0);
            #pragma unroll 4
            for (int j = 0; j < cnt; j++) {
                int s = __shfl_sync(0xffffffffu, sl, j);
                acc += G[(size_t)s * 32 + lane];
            }
        }
        float o = acc * g_dinv[node] + bias[lane];
        if (RELU) o = (o >= 0.f) ? o : 0.01f * o;
        out[(size_t)node * 32 + lane] = o;
    }
}

// ---------------------------------------------------------------- launch
extern "C" void kernel_launch(void* const* d_in, const int* in_sizes, int n_in,
                              void* d_out, int out_size) {
    const float* x  = (const float*)d_in[0];
    const void*  ei = d_in[1];
    const float* W1 = (const float*)d_in[2];
    const float* b1 = (const float*)d_in[3];
    const float* W2 = (const float*)d_in[4];
    const float* b2 = (const float*)d_in[5];
    const float* W3 = (const float*)d_in[6];
    const float* b3 = (const float*)d_in[7];
    float* out = (float*)d_out;

    int N = in_sizes[0] / 64;
    int E = in_sizes[1] / 2;

    float* emb1 = out;
    float* emb2 = out + (size_t)N * 64;
    float* emb3 = out + (size_t)N * 128;

    // dtype probe + CSR build (reused by all 3 layers)
    k_detect<<<1, 32>>>((const unsigned int*)ei);
    k_zero<<<(N + 255) / 256, 256>>>(N);
    k_count<<<(E + 255) / 256, 256>>>(ei, E, N);
    k_scan<<<1, 1024>>>(N);
    k_fill<<<(E + 255) / 256, 256>>>(ei, E, N);

    int agg_blocks = (N * 32 + 255) / 256;

    // layer 1: x[.,64] -> emb1[.,64], leaky relu
    k_gemm<64, 64><<<(N + 63) / 64, 256>>>(x, W1, N);
    k_agg<64, true><<<agg_blocks, 256>>>(b1, emb1, N);

    // layer 2: emb1 -> emb2[.,64], leaky relu
    k_gemm<64, 64><<<(N + 63) / 64, 256>>>(emb1, W2, N);
    k_agg<64, true><<<agg_blocks, 256>>>(b2, emb2, N);

    // layer 3: emb2 -> emb3[.,32], no relu
    k_gemm<64, 32><<<(N + 127) / 128, 256>>>(emb2, W3, N);
    k_agg<32, false><<<agg_blocks, 256>>>(b3, emb3, N);
}

// round 3
// speedup vs baseline: 1.8825x; 1.8825x over previous
#include <cuda_runtime.h>

// ===========================================================================
// GCN: 3 layers, pull-based CSR aggregation, no float atomics.
//   out_i = leakyrelu( dinv_i * ( sum_{e: dst=i} g[src_e] + g[i] ) + b )
//   with g = (h @ W) * dinv  (row-scaled in GEMM epilogue)
// Algebraically identical to D^-1/2 (A+I) D^-1/2 (hW) + b.
//
// R2: replaced the single-block k_scan (217us on one SM!) with a 3-phase
// multi-block scan (~6us).
// ===========================================================================

#define NMAX 100000
#define EMAX 1600000
#define SCAN_TILE 1024
#define NBLK ((NMAX + SCAN_TILE - 1) / SCAN_TILE)   // 98

__device__ int   g_is64;
__device__ int   g_deg[NMAX];
__device__ float g_dinv[NMAX];
__device__ int   g_offs[NMAX + 1];
__device__ int   g_cur[NMAX];
__device__ int   g_csrc[EMAX];
__device__ int   g_bsum[NBLK];
__device__ int   g_bpre[NBLK];
__device__ float g_G[(size_t)NMAX * 64];

// ---------------------------------------------------------------- dtype probe
// int64 entries < 2^31 have zero high words; int32 data there would be random
// node ids -> all-zero over 64 entries is impossible.
__global__ void k_detect(const unsigned int* __restrict__ w) {
    if (threadIdx.x == 0) {
        int ok = 1;
        #pragma unroll
        for (int i = 0; i < 64; i++) ok &= (w[2 * i + 1] == 0u);
        g_is64 = ok;
    }
}

__device__ __forceinline__ int load_idx(const void* ei, size_t pos, int is64) {
    if (is64) return (int)((const long long*)ei)[pos];
    return ((const int*)ei)[pos];
}

// ---------------------------------------------------------------- build CSR
__global__ void k_zero(int N) {
    int i = blockIdx.x * blockDim.x + threadIdx.x;
    if (i < N) g_deg[i] = 0;
}

__global__ void k_count(const void* __restrict__ ei, int E, int N) {
    int e = blockIdx.x * blockDim.x + threadIdx.x;
    if (e < E) {
        int is64 = g_is64;
        int dst = load_idx(ei, (size_t)E + e, is64);
        if ((unsigned)dst < (unsigned)N) atomicAdd(&g_deg[dst], 1);
    }
}

// phase 1: per-block degree sums (1024 threads, 1 elem each)
__global__ void k_part(int N) {
    int i = blockIdx.x * SCAN_TILE + threadIdx.x;
    int d = (i < N) ? g_deg[i] : 0;
    int lane = threadIdx.x & 31, wid = threadIdx.x >> 5;
    #pragma unroll
    for (int o = 16; o > 0; o >>= 1) d += __shfl_down_sync(0xffffffffu, d, o);
    __shared__ int ws[32];
    if (lane == 0) ws[wid] = d;
    __syncthreads();
    if (wid == 0) {
        int v = ws[lane];
        #pragma unroll
        for (int o = 16; o > 0; o >>= 1) v += __shfl_down_sync(0xffffffffu, v, o);
        if (lane == 0) g_bsum[blockIdx.x] = v;
    }
}

// phase 2: single tiny block scans NBLK (<=128) partials -> exclusive prefixes
__global__ void k_scanb() {
    int t = threadIdx.x;                      // 128 threads
    int v = (t < NBLK) ? g_bsum[t] : 0;
    int lane = t & 31, wid = t >> 5;
    int s = v;
    #pragma unroll
    for (int o = 1; o < 32; o <<= 1) {
        int u = __shfl_up_sync(0xffffffffu, s, o);
        if (lane >= o) s += u;
    }
    __shared__ int ws[4];
    if (lane == 31) ws[wid] = s;
    __syncthreads();
    int wpre = 0;
    for (int w = 0; w < wid; w++) wpre += ws[w];
    if (t < NBLK) g_bpre[t] = s - v + wpre;   // exclusive
}

// phase 3: block-wide exclusive scan of degrees + block prefix -> offs/cur/dinv
__global__ void k_offs(int N, int E) {
    int i = blockIdx.x * SCAN_TILE + threadIdx.x;
    int d = (i < N) ? g_deg[i] : 0;
    int lane = threadIdx.x & 31, wid = threadIdx.x >> 5;
    int v = d;
    #pragma unroll
    for (int o = 1; o < 32; o <<= 1) {
        int u = __shfl_up_sync(0xffffffffu, v, o);
        if (lane >= o) v += u;
    }
    __shared__ int ws[32];
    if (lane == 31) ws[wid] = v;
    __syncthreads();
    if (wid == 0) {
        int w = ws[lane];
        #pragma unroll
        for (int o = 1; o < 32; o <<= 1) {
            int u = __shfl_up_sync(0xffffffffu, w, o);
            if (lane >= o) w += u;
        }
        ws[lane] = w;
    }
    __syncthreads();
    int incl = v + ((wid > 0) ? ws[wid - 1] : 0);
    int excl = incl - d + g_bpre[blockIdx.x];
    if (i < N) {
        g_offs[i] = excl;
        g_cur[i]  = excl;
        g_dinv[i] = rsqrtf((float)(d + 1));   // +1 self loop
        if (i == N - 1) g_offs[N] = excl + d; // == E
    }
}

__global__ void k_fill(const void* __restrict__ ei, int E, int N) {
    int e = blockIdx.x * blockDim.x + threadIdx.x;
    if (e < E) {
        int is64 = g_is64;
        int dst = load_idx(ei, (size_t)E + e, is64);
        int src = load_idx(ei, (size_t)e, is64);
        if ((unsigned)dst < (unsigned)N) {
            int pos = atomicAdd(&g_cur[dst], 1);
            g_csrc[pos] = ((unsigned)src < (unsigned)N) ? src : 0;
        }
    }
}

// ---------------------------------------------------------------- GEMM
// g = (X @ W) * dinv[row]    X:[N,DIN] W:[DIN,DOUT] -> g_G:[N,DOUT]
template <int DIN, int DOUT>
__global__ void k_gemm(const float* __restrict__ X, const float* __restrict__ W, int N) {
    __shared__ float sW[DIN * DOUT];
    for (int i = threadIdx.x; i < DIN * DOUT; i += blockDim.x) sW[i] = W[i];
    __syncthreads();

    constexpr int CG  = DOUT / 4;     // col groups of 4
    constexpr int RPB = (256 / CG) * 4;
    int jg   = threadIdx.x % CG;
    int ig   = threadIdx.x / CG;
    int row0 = blockIdx.x * RPB + ig * 4;
    if (row0 >= N) return;

    if (row0 + 4 <= N) {
        float4 acc[4];
        #pragma unroll
        for (int r = 0; r < 4; r++) acc[r] = make_float4(0.f, 0.f, 0.f, 0.f);
        for (int k0 = 0; k0 < DIN; k0 += 4) {
            float4 xv[4];
            #pragma unroll
            for (int r = 0; r < 4; r++)
                xv[r] = *(const float4*)(X + (size_t)(row0 + r) * DIN + k0);
            #pragma unroll
            for (int kk = 0; kk < 4; kk++) {
                float4 w = *(const float4*)(sW + (k0 + kk) * DOUT + jg * 4);
                #pragma unroll
                for (int r = 0; r < 4; r++) {
                    float xs = (kk == 0) ? xv[r].x : (kk == 1) ? xv[r].y
                             : (kk == 2) ? xv[r].z : xv[r].w;
                    acc[r].x += xs * w.x;
                    acc[r].y += xs * w.y;
                    acc[r].z += xs * w.z;
                    acc[r].w += xs * w.w;
                }
            }
        }
        #pragma unroll
        for (int r = 0; r < 4; r++) {
            float sc = g_dinv[row0 + r];
            float4 o = make_float4(acc[r].x * sc, acc[r].y * sc,
                                   acc[r].z * sc, acc[r].w * sc);
            *(float4*)(g_G + (size_t)(row0 + r) * DOUT + jg * 4) = o;
        }
    } else {
        for (int r = 0; r < 4; r++) {
            int row = row0 + r;
            if (row >= N) break;
            float a0 = 0.f, a1 = 0.f, a2 = 0.f, a3 = 0.f;
            for (int k = 0; k < DIN; k++) {
                float xs = X[(size_t)row * DIN + k];
                const float* w = sW + k * DOUT + jg * 4;
                a0 += xs * w[0]; a1 += xs * w[1]; a2 += xs * w[2]; a3 += xs * w[3];
            }
            float sc = g_dinv[row];
            float4 o = make_float4(a0 * sc, a1 * sc, a2 * sc, a3 * sc);
            *(float4*)(g_G + (size_t)row * DOUT + jg * 4) = o;
        }
    }
}

// ---------------------------------------------------------------- aggregate
// warp-per-node pull reduction. D=64: lane holds float2; D=32: lane holds float.
template <int D, bool RELU>
__global__ void k_agg(const float* __restrict__ bias, float* __restrict__ out, int N) {
    int gid  = blockIdx.x * blockDim.x + threadIdx.x;
    int node = gid >> 5;
    int lane = gid & 31;
    if (node >= N) return;  // warp-uniform

    const float* __restrict__ G = g_G;
    int beg = g_offs[node];
    int end = g_offs[node + 1];

    if (D == 64) {
        float2 acc = *(const float2*)(G + (size_t)node * 64 + lane * 2);  // self loop
        for (int e0 = beg; e0 < end; e0 += 32) {
            int idx = e0 + lane;
            int sl  = (idx < end) ? g_csrc[idx] : 0;
            int cnt = min(32, end - e0);
            #pragma unroll 4
            for (int j = 0; j < cnt; j++) {
                int s = __shfl_sync(0xffffffffu, sl, j);
                float2 v = *(const float2*)(G + (size_t)s * 64 + lane * 2);
                acc.x += v.x;
                acc.y += v.y;
            }
        }
        float  sc = g_dinv[node];
        float2 b  = *(const float2*)(bias + lane * 2);
        float ox = acc.x * sc + b.x;
        float oy = acc.y * sc + b.y;
        if (RELU) {
            ox = (ox >= 0.f) ? ox : 0.01f * ox;
            oy = (oy >= 0.f) ? oy : 0.01f * oy;
        }
        *(float2*)(out + (size_t)node * 64 + lane * 2) = make_float2(ox, oy);
    } else {  // D == 32
        float acc = G[(size_t)node * 32 + lane];
        for (int e0 = beg; e0 < end; e0 += 32) {
            int idx = e0 + lane;
            int sl  = (idx < end) ? g_csrc[idx] : 0;
            int cnt = min(32, end - e0);
            #pragma unroll 4
            for (int j = 0; j < cnt; j++) {
                int s = __shfl_sync(0xffffffffu, sl, j);
                acc += G[(size_t)s * 32 + lane];
            }
        }
        float o = acc * g_dinv[node] + bias[lane];
        if (RELU) o = (o >= 0.f) ? o : 0.01f * o;
        out[(size_t)node * 32 + lane] = o;
    }
}

// ---------------------------------------------------------------- launch
extern "C" void kernel_launch(void* const* d_in, const int* in_sizes, int n_in,
                              void* d_out, int out_size) {
    const float* x  = (const float*)d_in[0];
    const void*  ei = d_in[1];
    const float* W1 = (const float*)d_in[2];
    const float* b1 = (const float*)d_in[3];
    const float* W2 = (const float*)d_in[4];
    const float* b2 = (const float*)d_in[5];
    const float* W3 = (const float*)d_in[6];
    const float* b3 = (const float*)d_in[7];
    float* out = (float*)d_out;

    int N = in_sizes[0] / 64;
    int E = in_sizes[1] / 2;

    float* emb1 = out;
    float* emb2 = out + (size_t)N * 64;
    float* emb3 = out + (size_t)N * 128;

    int nblk = (N + SCAN_TILE - 1) / SCAN_TILE;

    // dtype probe + CSR build (reused by all 3 layers)
    k_detect<<<1, 32>>>((const unsigned int*)ei);
    k_zero<<<(N + 255) / 256, 256>>>(N);
    k_count<<<(E + 255) / 256, 256>>>(ei, E, N);
    k_part<<<nblk, SCAN_TILE>>>(N);
    k_scanb<<<1, 128>>>();
    k_offs<<<nblk, SCAN_TILE>>>(N, E);
    k_fill<<<(E + 255) / 256, 256>>>(ei, E, N);

    int agg_blocks = (N * 32 + 255) / 256;

    // layer 1: x[.,64] -> emb1[.,64], leaky relu
    k_gemm<64, 64><<<(N + 63) / 64, 256>>>(x, W1, N);
    k_agg<64, true><<<agg_blocks, 256>>>(b1, emb1, N);

    // layer 2: emb1 -> emb2[.,64], leaky relu
    k_gemm<64, 64><<<(N + 63) / 64, 256>>>(emb1, W2, N);
    k_agg<64, true><<<agg_blocks, 256>>>(b2, emb2, N);

    // layer 3: emb2 -> emb3[.,32], no relu
    k_gemm<64, 32><<<(N + 127) / 128, 256>>>(emb2, W3, N);
    k_agg<32, false><<<agg_blocks, 256>>>(b3, emb3, N);
}

// round 4
// speedup vs baseline: 1.8878x; 1.0028x over previous
#include <cuda_runtime.h>
#include <cuda_fp16.h>

// ===========================================================================
// GCN: 3 layers, pull-based CSR aggregation, no float atomics.
//   out_i = leakyrelu( dinv_i * ( sum_{e: dst=i} g[src_e] + g[i] ) + b )
//   with g = (h @ W) * dinv  (row-scaled in GEMM epilogue)
// Algebraically identical to D^-1/2 (A+I) D^-1/2 (hW) + b.
//
// R2: 3-phase multi-block scan (was 217us single-block -> ~6us).
// R4: gather table G stored in fp16 (fp32 accumulate) -> halves the
//     L2 gather traffic that dominates runtime.
// ===========================================================================

#define NMAX 100000
#define EMAX 1600000
#define SCAN_TILE 1024
#define NBLK ((NMAX + SCAN_TILE - 1) / SCAN_TILE)   // 98

__device__ int    g_is64;
__device__ int    g_deg[NMAX];
__device__ float  g_dinv[NMAX];
__device__ int    g_offs[NMAX + 1];
__device__ int    g_cur[NMAX];
__device__ int    g_csrc[EMAX];
__device__ int    g_bsum[NBLK];
__device__ int    g_bpre[NBLK];
__device__ __half g_Gh[(size_t)NMAX * 64];   // fp16 gather table

// ---------------------------------------------------------------- dtype probe
// int64 entries < 2^31 have zero high words; int32 data there would be random
// node ids -> all-zero over 64 entries is impossible.
__global__ void k_detect(const unsigned int* __restrict__ w) {
    if (threadIdx.x == 0) {
        int ok = 1;
        #pragma unroll
        for (int i = 0; i < 64; i++) ok &= (w[2 * i + 1] == 0u);
        g_is64 = ok;
    }
}

__device__ __forceinline__ int load_idx(const void* ei, size_t pos, int is64) {
    if (is64) return (int)((const long long*)ei)[pos];
    return ((const int*)ei)[pos];
}

// ---------------------------------------------------------------- build CSR
__global__ void k_zero(int N) {
    int i = blockIdx.x * blockDim.x + threadIdx.x;
    if (i < N) g_deg[i] = 0;
}

__global__ void k_count(const void* __restrict__ ei, int E, int N) {
    int e = blockIdx.x * blockDim.x + threadIdx.x;
    if (e < E) {
        int is64 = g_is64;
        int dst = load_idx(ei, (size_t)E + e, is64);
        if ((unsigned)dst < (unsigned)N) atomicAdd(&g_deg[dst], 1);
    }
}

// phase 1: per-block degree sums
__global__ void k_part(int N) {
    int i = blockIdx.x * SCAN_TILE + threadIdx.x;
    int d = (i < N) ? g_deg[i] : 0;
    int lane = threadIdx.x & 31, wid = threadIdx.x >> 5;
    #pragma unroll
    for (int o = 16; o > 0; o >>= 1) d += __shfl_down_sync(0xffffffffu, d, o);
    __shared__ int ws[32];
    if (lane == 0) ws[wid] = d;
    __syncthreads();
    if (wid == 0) {
        int v = ws[lane];
        #pragma unroll
        for (int o = 16; o > 0; o >>= 1) v += __shfl_down_sync(0xffffffffu, v, o);
        if (lane == 0) g_bsum[blockIdx.x] = v;
    }
}

// phase 2: single tiny block scans NBLK partials -> exclusive prefixes
__global__ void k_scanb() {
    int t = threadIdx.x;                      // 128 threads
    int v = (t < NBLK) ? g_bsum[t] : 0;
    int lane = t & 31, wid = t >> 5;
    int s = v;
    #pragma unroll
    for (int o = 1; o < 32; o <<= 1) {
        int u = __shfl_up_sync(0xffffffffu, s, o);
        if (lane >= o) s += u;
    }
    __shared__ int ws[4];
    if (lane == 31) ws[wid] = s;
    __syncthreads();
    int wpre = 0;
    for (int w = 0; w < wid; w++) wpre += ws[w];
    if (t < NBLK) g_bpre[t] = s - v + wpre;   // exclusive
}

// phase 3: block-wide exclusive scan of degrees + block prefix
__global__ void k_offs(int N, int E) {
    int i = blockIdx.x * SCAN_TILE + threadIdx.x;
    int d = (i < N) ? g_deg[i] : 0;
    int lane = threadIdx.x & 31, wid = threadIdx.x >> 5;
    int v = d;
    #pragma unroll
    for (int o = 1; o < 32; o <<= 1) {
        int u = __shfl_up_sync(0xffffffffu, v, o);
        if (lane >= o) v += u;
    }
    __shared__ int ws[32];
    if (lane == 31) ws[wid] = v;
    __syncthreads();
    if (wid == 0) {
        int w = ws[lane];
        #pragma unroll
        for (int o = 1; o < 32; o <<= 1) {
            int u = __shfl_up_sync(0xffffffffu, w, o);
            if (lane >= o) w += u;
        }
        ws[lane] = w;
    }
    __syncthreads();
    int incl = v + ((wid > 0) ? ws[wid - 1] : 0);
    int excl = incl - d + g_bpre[blockIdx.x];
    if (i < N) {
        g_offs[i] = excl;
        g_cur[i]  = excl;
        g_dinv[i] = rsqrtf((float)(d + 1));   // +1 self loop
        if (i == N - 1) g_offs[N] = excl + d; // == E
    }
}

__global__ void k_fill(const void* __restrict__ ei, int E, int N) {
    int e = blockIdx.x * blockDim.x + threadIdx.x;
    if (e < E) {
        int is64 = g_is64;
        int dst = load_idx(ei, (size_t)E + e, is64);
        int src = load_idx(ei, (size_t)e, is64);
        if ((unsigned)dst < (unsigned)N) {
            int pos = atomicAdd(&g_cur[dst], 1);
            g_csrc[pos] = ((unsigned)src < (unsigned)N) ? src : 0;
        }
    }
}

// ---------------------------------------------------------------- GEMM
// g_Gh = fp16( (X @ W) * dinv[row] )   X:[N,DIN] fp32, W:[DIN,DOUT]
template <int DIN, int DOUT>
__global__ void k_gemm(const float* __restrict__ X, const float* __restrict__ W, int N) {
    __shared__ float sW[DIN * DOUT];
    for (int i = threadIdx.x; i < DIN * DOUT; i += blockDim.x) sW[i] = W[i];
    __syncthreads();

    constexpr int CG  = DOUT / 4;     // col groups of 4
    constexpr int RPB = (256 / CG) * 4;
    int jg   = threadIdx.x % CG;
    int ig   = threadIdx.x / CG;
    int row0 = blockIdx.x * RPB + ig * 4;
    if (row0 >= N) return;

    __half2* Gh2 = (__half2*)g_Gh;

    if (row0 + 4 <= N) {
        float4 acc[4];
        #pragma unroll
        for (int r = 0; r < 4; r++) acc[r] = make_float4(0.f, 0.f, 0.f, 0.f);
        for (int k0 = 0; k0 < DIN; k0 += 4) {
            float4 xv[4];
            #pragma unroll
            for (int r = 0; r < 4; r++)
                xv[r] = *(const float4*)(X + (size_t)(row0 + r) * DIN + k0);
            #pragma unroll
            for (int kk = 0; kk < 4; kk++) {
                float4 w = *(const float4*)(sW + (k0 + kk) * DOUT + jg * 4);
                #pragma unroll
                for (int r = 0; r < 4; r++) {
                    float xs = (kk == 0) ? xv[r].x : (kk == 1) ? xv[r].y
                             : (kk == 2) ? xv[r].z : xv[r].w;
                    acc[r].x += xs * w.x;
                    acc[r].y += xs * w.y;
                    acc[r].z += xs * w.z;
                    acc[r].w += xs * w.w;
                }
            }
        }
        #pragma unroll
        for (int r = 0; r < 4; r++) {
            float sc = g_dinv[row0 + r];
            size_t base = ((size_t)(row0 + r) * DOUT) / 2 + jg * 2;
            Gh2[base]     = __floats2half2_rn(acc[r].x * sc, acc[r].y * sc);
            Gh2[base + 1] = __floats2half2_rn(acc[r].z * sc, acc[r].w * sc);
        }
    } else {
        for (int r = 0; r < 4; r++) {
            int row = row0 + r;
            if (row >= N) break;
            float a0 = 0.f, a1 = 0.f, a2 = 0.f, a3 = 0.f;
            for (int k = 0; k < DIN; k++) {
                float xs = X[(size_t)row * DIN + k];
                const float* w = sW + k * DOUT + jg * 4;
                a0 += xs * w[0]; a1 += xs * w[1]; a2 += xs * w[2]; a3 += xs * w[3];
            }
            float sc = g_dinv[row];
            size_t base = ((size_t)row * DOUT) / 2 + jg * 2;
            Gh2[base]     = __floats2half2_rn(a0 * sc, a1 * sc);
            Gh2[base + 1] = __floats2half2_rn(a2 * sc, a3 * sc);
        }
    }
}

// ---------------------------------------------------------------- aggregate
// warp-per-node pull reduction over fp16 table, fp32 accumulate.
// D=64: lane holds half2 (2 feats); D=32: lane holds one half.
template <int D, bool RELU>
__global__ void k_agg(const float* __restrict__ bias, float* __restrict__ out, int N) {
    int gid  = blockIdx.x * blockDim.x + threadIdx.x;
    int node = gid >> 5;
    int lane = gid & 31;
    if (node >= N) return;  // warp-uniform

    int beg = g_offs[node];
    int end = g_offs[node + 1];

    if (D == 64) {
        const __half2* __restrict__ G = (const __half2*)g_Gh;  // row stride 32
        float2 acc = __half22float2(G[(size_t)node * 32 + lane]);  // self loop
        for (int e0 = beg; e0 < end; e0 += 32) {
            int idx = e0 + lane;
            int sl  = (idx < end) ? g_csrc[idx] : 0;
            int cnt = min(32, end - e0);
            #pragma unroll 4
            for (int j = 0; j < cnt; j++) {
                int s = __shfl_sync(0xffffffffu, sl, j);
                float2 v = __half22float2(G[(size_t)s * 32 + lane]);
                acc.x += v.x;
                acc.y += v.y;
            }
        }
        float  sc = g_dinv[node];
        float2 b  = *(const float2*)(bias + lane * 2);
        float ox = acc.x * sc + b.x;
        float oy = acc.y * sc + b.y;
        if (RELU) {
            ox = (ox >= 0.f) ? ox : 0.01f * ox;
            oy = (oy >= 0.f) ? oy : 0.01f * oy;
        }
        *(float2*)(out + (size_t)node * 64 + lane * 2) = make_float2(ox, oy);
    } else {  // D == 32
        const __half* __restrict__ G = g_Gh;  // row stride 32 halves
        float acc = __half2float(G[(size_t)node * 32 + lane]);
        for (int e0 = beg; e0 < end; e0 += 32) {
            int idx = e0 + lane;
            int sl  = (idx < end) ? g_csrc[idx] : 0;
            int cnt = min(32, end - e0);
            #pragma unroll 4
            for (int j = 0; j < cnt; j++) {
                int s = __shfl_sync(0xffffffffu, sl, j);
                acc += __half2float(G[(size_t)s * 32 + lane]);
            }
        }
        float o = acc * g_dinv[node] + bias[lane];
        if (RELU) o = (o >= 0.f) ? o : 0.01f * o;
        out[(size_t)node * 32 + lane] = o;
    }
}

// ---------------------------------------------------------------- launch
extern "C" void kernel_launch(void* const* d_in, const int* in_sizes, int n_in,
                              void* d_out, int out_size) {
    const float* x  = (const float*)d_in[0];
    const void*  ei = d_in[1];
    const float* W1 = (const float*)d_in[2];
    const float* b1 = (const float*)d_in[3];
    const float* W2 = (const float*)d_in[4];
    const float* b2 = (const float*)d_in[5];
    const float* W3 = (const float*)d_in[6];
    const float* b3 = (const float*)d_in[7];
    float* out = (float*)d_out;

    int N = in_sizes[0] / 64;
    int E = in_sizes[1] / 2;

    float* emb1 = out;
    float* emb2 = out + (size_t)N * 64;
    float* emb3 = out + (size_t)N * 128;

    int nblk = (N + SCAN_TILE - 1) / SCAN_TILE;

    // dtype probe + CSR build (reused by all 3 layers)
    k_detect<<<1, 32>>>((const unsigned int*)ei);
    k_zero<<<(N + 255) / 256, 256>>>(N);
    k_count<<<(E + 255) / 256, 256>>>(ei, E, N);
    k_part<<<nblk, SCAN_TILE>>>(N);
    k_scanb<<<1, 128>>>();
    k_offs<<<nblk, SCAN_TILE>>>(N, E);
    k_fill<<<(E + 255) / 256, 256>>>(ei, E, N);

    int agg_blocks = (N * 32 + 255) / 256;

    // layer 1: x[.,64] -> emb1[.,64], leaky relu
    k_gemm<64, 64><<<(N + 63) / 64, 256>>>(x, W1, N);
    k_agg<64, true><<<agg_blocks, 256>>>(b1, emb1, N);

    // layer 2: emb1 -> emb2[.,64], leaky relu
    k_gemm<64, 64><<<(N + 63) / 64, 256>>>(emb1, W2, N);
    k_agg<64, true><<<agg_blocks, 256>>>(b2, emb2, N);

    // layer 3: emb2 -> emb3[.,32], no relu
    k_gemm<64, 32><<<(N + 127) / 128, 256>>>(emb2, W3, N);
    k_agg<32, false><<<agg_blocks, 256>>>(b3, emb3, N);
}

// round 5
// speedup vs baseline: 2.0445x; 1.0830x over previous
#include <cuda_runtime.h>
#include <cuda_fp16.h>

// ===========================================================================
// GCN: 3 layers, pull-based padded-CSR aggregation, no float atomics.
//   out_i = leakyrelu( dinv_i * ( sum_{e: dst=i} g[src_e] + g[i] ) + b )
//   with g = fp16( (h @ W) * dinv )  (row-scaled in GEMM epilogue)
//
// R2: multi-block scan. R4: fp16 gather table.
// R5: - edge lists padded to multiple of 8 with sentinel->zero row
//     - agg processes 4 (D=64) / 8 (D=32) edges per warp-iteration with
//       LDG.128 gathers (cuts per-edge instruction count 2-3x; aggs proved
//       issue-bound, not BW-bound, by the R4 null result)
//     - 10 launches (probe inlined, scan fused into offs, deg re-zeroed
//       in offs); gemm1 moved to launch slot 4 for ncu capture
// ===========================================================================

#define NMAX 100000
#define EMAX 1600000
#define PADMAX (EMAX + 8 * NMAX)
#define SCAN_TILE 1024
#define NBLK ((NMAX + SCAN_TILE - 1) / SCAN_TILE)   // 98

__device__ int    g_deg[NMAX];                   // .bss zero; re-zeroed by k_offs
__device__ float  g_dinv[NMAX];
__device__ int    g_offs[NMAX + 1];              // padded CSR offsets
__device__ int    g_cur[NMAX];
__device__ int    g_csrc[PADMAX];
__device__ int    g_bsum[NBLK];
__device__ __half g_Gh[(size_t)(NMAX + 1) * 64]; // +1: tail zero row (sentinel)

// per-warp dtype probe: int64 entries < 2^31 have zero high words; for int32
// data those words are random node ids -> 16 zeros is impossible.
__device__ __forceinline__ int probe_is64(const unsigned* w, int lane) {
    unsigned hw = w[2 * (lane & 15) + 1];
    return __ballot_sync(0xffffffffu, hw == 0u) == 0xffffffffu;
}

__device__ __forceinline__ int load_idx(const void* ei, size_t pos, int is64) {
    if (is64) return (int)((const long long*)ei)[pos];
    return ((const int*)ei)[pos];
}

// ---------------------------------------------------------------- CSR build
__global__ void k_count(const void* __restrict__ ei, int E, int N) {
    int lane = threadIdx.x & 31;
    int is64 = probe_is64((const unsigned*)ei, lane);
    int e = blockIdx.x * blockDim.x + threadIdx.x;
    if (e < E) {
        int dst = load_idx(ei, (size_t)E + e, is64);
        if ((unsigned)dst < (unsigned)N) atomicAdd(&g_deg[dst], 1);
    }
}

// per-block sums of PADDED degrees
__global__ void k_part(int N) {
    int i = blockIdx.x * SCAN_TILE + threadIdx.x;
    int d  = (i < N) ? g_deg[i] : 0;
    int pd = (d + 7) & ~7;
    int lane = threadIdx.x & 31, wid = threadIdx.x >> 5;
    #pragma unroll
    for (int o = 16; o > 0; o >>= 1) pd += __shfl_down_sync(0xffffffffu, pd, o);
    __shared__ int ws[32];
    if (lane == 0) ws[wid] = pd;
    __syncthreads();
    if (wid == 0) {
        int v = ws[lane];
        #pragma unroll
        for (int o = 16; o > 0; o >>= 1) v += __shfl_down_sync(0xffffffffu, v, o);
        if (lane == 0) g_bsum[blockIdx.x] = v;
    }
}

// fused: scan of block sums + block-wide scan of padded degrees ->
// offs/cur/dinv, sentinel pad fill, and re-zero g_deg for the next call.
__global__ void k_offs(int N) {
    __shared__ int sb[128];
    __shared__ int ws[32];
    int t = threadIdx.x;

    // 128-thread inclusive scan of NBLK block sums (warps 0-3)
    if (t < 128) {
        int v = (t < NBLK) ? g_bsum[t] : 0;
        int lane = t & 31, w = t >> 5;
        int s = v;
        #pragma unroll
        for (int o = 1; o < 32; o <<= 1) {
            int u = __shfl_up_sync(0xffffffffu, s, o);
            if (lane >= o) s += u;
        }
        if (lane == 31) ws[w] = s;
        sb[t] = s;
    }
    __syncthreads();
    if (t < 128) {
        int w = t >> 5;
        int add = 0;
        for (int q = 0; q < w; q++) add += ws[q];
        sb[t] += add;
    }
    __syncthreads();
    int blockpre = (blockIdx.x == 0) ? 0 : sb[blockIdx.x - 1];
    __syncthreads();  // ws reused below

    // block-wide scan of padded degrees
    int i = blockIdx.x * SCAN_TILE + t;
    int d  = (i < N) ? g_deg[i] : 0;
    int pd = (d + 7) & ~7;
    int lane = t & 31, wid = t >> 5;
    int v = pd;
    #pragma unroll
    for (int o = 1; o < 32; o <<= 1) {
        int u = __shfl_up_sync(0xffffffffu, v, o);
        if (lane >= o) v += u;
    }
    if (lane == 31) ws[wid] = v;
    __syncthreads();
    if (wid == 0) {
        int w = ws[lane];
        #pragma unroll
        for (int o = 1; o < 32; o <<= 1) {
            int u = __shfl_up_sync(0xffffffffu, w, o);
            if (lane >= o) w += u;
        }
        ws[lane] = w;
    }
    __syncthreads();
    int incl = v + ((wid > 0) ? ws[wid - 1] : 0);
    int excl = incl - pd + blockpre;
    if (i < N) {
        g_offs[i] = excl;
        g_cur[i]  = excl;
        g_dinv[i] = rsqrtf((float)(d + 1));     // +1 self loop (real degree)
        for (int p = excl + d; p < excl + pd; p++) g_csrc[p] = NMAX;  // sentinel
        g_deg[i] = 0;                            // ready for next replay
        if (i == N - 1) g_offs[N] = excl + pd;
    }
}

__global__ void k_fill(const void* __restrict__ ei, int E, int N) {
    int lane = threadIdx.x & 31;
    int is64 = probe_is64((const unsigned*)ei, lane);
    int e = blockIdx.x * blockDim.x + threadIdx.x;
    if (e < E) {
        int dst = load_idx(ei, (size_t)E + e, is64);
        int src = load_idx(ei, (size_t)e, is64);
        if ((unsigned)dst < (unsigned)N) {
            int pos = atomicAdd(&g_cur[dst], 1);
            g_csrc[pos] = ((unsigned)src < (unsigned)N) ? src : 0;
        }
    }
}

// ---------------------------------------------------------------- GEMM
// g_Gh = fp16( (X @ W) * dinv[row] )
template <int DIN, int DOUT>
__global__ void k_gemm(const float* __restrict__ X, const float* __restrict__ W, int N) {
    __shared__ float sW[DIN * DOUT];
    for (int i = threadIdx.x; i < DIN * DOUT; i += blockDim.x) sW[i] = W[i];
    __syncthreads();

    constexpr int CG  = DOUT / 4;
    constexpr int RPB = (256 / CG) * 4;
    int jg   = threadIdx.x % CG;
    int ig   = threadIdx.x / CG;
    int row0 = blockIdx.x * RPB + ig * 4;
    if (row0 >= N) return;

    __half2* Gh2 = (__half2*)g_Gh;

    if (row0 + 4 <= N) {
        float4 acc[4];
        #pragma unroll
        for (int r = 0; r < 4; r++) acc[r] = make_float4(0.f, 0.f, 0.f, 0.f);
        for (int k0 = 0; k0 < DIN; k0 += 4) {
            float4 xv[4];
            #pragma unroll
            for (int r = 0; r < 4; r++)
                xv[r] = *(const float4*)(X + (size_t)(row0 + r) * DIN + k0);
            #pragma unroll
            for (int kk = 0; kk < 4; kk++) {
                float4 w = *(const float4*)(sW + (k0 + kk) * DOUT + jg * 4);
                #pragma unroll
                for (int r = 0; r < 4; r++) {
                    float xs = (kk == 0) ? xv[r].x : (kk == 1) ? xv[r].y
                             : (kk == 2) ? xv[r].z : xv[r].w;
                    acc[r].x += xs * w.x;
                    acc[r].y += xs * w.y;
                    acc[r].z += xs * w.z;
                    acc[r].w += xs * w.w;
                }
            }
        }
        #pragma unroll
        for (int r = 0; r < 4; r++) {
            float sc = g_dinv[row0 + r];
            size_t base = ((size_t)(row0 + r) * DOUT) / 2 + jg * 2;
            Gh2[base]     = __floats2half2_rn(acc[r].x * sc, acc[r].y * sc);
            Gh2[base + 1] = __floats2half2_rn(acc[r].z * sc, acc[r].w * sc);
        }
    } else {
        for (int r = 0; r < 4; r++) {
            int row = row0 + r;
            if (row >= N) break;
            float a0 = 0.f, a1 = 0.f, a2 = 0.f, a3 = 0.f;
            for (int k = 0; k < DIN; k++) {
                float xs = X[(size_t)row * DIN + k];
                const float* w = sW + k * DOUT + jg * 4;
                a0 += xs * w[0]; a1 += xs * w[1]; a2 += xs * w[2]; a3 += xs * w[3];
            }
            float sc = g_dinv[row];
            size_t base = ((size_t)row * DOUT) / 2 + jg * 2;
            Gh2[base]     = __floats2half2_rn(a0 * sc, a1 * sc);
            Gh2[base + 1] = __floats2half2_rn(a2 * sc, a3 * sc);
        }
    }
}

// ---------------------------------------------------------------- aggregate
// D=64: warp-per-node, 4 edges/iter. 8 lanes per row, each lane LDG.128
// (8 halves = 8 feats). fp32 accumulate, shfl_xor cross-group reduce.
template <bool RELU>
__global__ void k_agg64(const float* __restrict__ bias, float* __restrict__ out, int N) {
    int gid  = blockIdx.x * blockDim.x + threadIdx.x;
    int node = gid >> 5;
    int lane = gid & 31;
    if (node >= N) return;

    const uint4* __restrict__ G4 = (const uint4*)g_Gh;  // row = 8 granules
    int sub = lane & 7;   // 16B granule within row
    int grp = lane >> 3;  // edge group 0..3
    int beg = g_offs[node];
    int end = g_offs[node + 1];

    float acc[8];
    #pragma unroll
    for (int k = 0; k < 8; k++) acc[k] = 0.f;

    for (int e0 = beg; e0 < end; e0 += 32) {
        int idx = e0 + lane;
        int sl  = (idx < end) ? g_csrc[idx] : NMAX;
        int cnt = min(32, end - e0);          // multiple of 8
        for (int j = 0; j < cnt; j += 4) {
            int s = __shfl_sync(0xffffffffu, sl, j + grp);
            uint4 v = G4[(size_t)s * 8 + sub];
            const __half2* h = (const __half2*)&v;
            #pragma unroll
            for (int q = 0; q < 4; q++) {
                float2 f = __half22float2(h[q]);
                acc[2 * q]     += f.x;
                acc[2 * q + 1] += f.y;
            }
        }
    }
    // combine 4 edge groups
    #pragma unroll
    for (int k = 0; k < 8; k++) {
        acc[k] += __shfl_xor_sync(0xffffffffu, acc[k], 8);
        acc[k] += __shfl_xor_sync(0xffffffffu, acc[k], 16);
    }
    // self loop (post-reduction: each lane adds once)
    {
        uint4 v = G4[(size_t)node * 8 + sub];
        const __half2* h = (const __half2*)&v;
        #pragma unroll
        for (int q = 0; q < 4; q++) {
            float2 f = __half22float2(h[q]);
            acc[2 * q]     += f.x;
            acc[2 * q + 1] += f.y;
        }
    }
    if (lane < 8) {
        float sc = g_dinv[node];
        float o[8];
        #pragma unroll
        for (int k = 0; k < 8; k++) {
            o[k] = acc[k] * sc + bias[lane * 8 + k];
            if (RELU) o[k] = (o[k] >= 0.f) ? o[k] : 0.01f * o[k];
        }
        float* dst = out + (size_t)node * 64 + lane * 8;
        *(float4*)(dst)     = make_float4(o[0], o[1], o[2], o[3]);
        *(float4*)(dst + 4) = make_float4(o[4], o[5], o[6], o[7]);
    }
}

// D=32: warp-per-node, 8 edges/iter. 4 lanes per row, lane LDG.128 = 8 feats.
// Sentinel remapped to the zero tail row (NMAX*8 in uint4 units).
template <bool RELU>
__global__ void k_agg32(const float* __restrict__ bias, float* __restrict__ out, int N) {
    int gid  = blockIdx.x * blockDim.x + threadIdx.x;
    int node = gid >> 5;
    int lane = gid & 31;
    if (node >= N) return;

    const uint4* __restrict__ G4 = (const uint4*)g_Gh;  // row = 4 granules
    int sub = lane & 3;
    int grp = lane >> 2;  // 0..7
    int beg = g_offs[node];
    int end = g_offs[node + 1];

    float acc[8];
    #pragma unroll
    for (int k = 0; k < 8; k++) acc[k] = 0.f;

    for (int e0 = beg; e0 < end; e0 += 32) {
        int idx = e0 + lane;
        int sl  = (idx < end) ? g_csrc[idx] : NMAX;
        int cnt = min(32, end - e0);          // multiple of 8
        for (int j = 0; j < cnt; j += 8) {
            int s = __shfl_sync(0xffffffffu, sl, j + grp);
            size_t rb = (s == NMAX) ? ((size_t)NMAX * 8) : ((size_t)s * 4);
            uint4 v = G4[rb + sub];
            const __half2* h = (const __half2*)&v;
            #pragma unroll
            for (int q = 0; q < 4; q++) {
                float2 f = __half22float2(h[q]);
                acc[2 * q]     += f.x;
                acc[2 * q + 1] += f.y;
            }
        }
    }
    #pragma unroll
    for (int k = 0; k < 8; k++) {
        acc[k] += __shfl_xor_sync(0xffffffffu, acc[k], 4);
        acc[k] += __shfl_xor_sync(0xffffffffu, acc[k], 8);
        acc[k] += __shfl_xor_sync(0xffffffffu, acc[k], 16);
    }
    {
        uint4 v = G4[(size_t)node * 4 + sub];
        const __half2* h = (const __half2*)&v;
        #pragma unroll
        for (int q = 0; q < 4; q++) {
            float2 f = __half22float2(h[q]);
            acc[2 * q]     += f.x;
            acc[2 * q + 1] += f.y;
        }
    }
    if (lane < 4) {
        float sc = g_dinv[node];
        float o[8];
        #pragma unroll
        for (int k = 0; k < 8; k++) {
            o[k] = acc[k] * sc + bias[lane * 8 + k];
            if (RELU) o[k] = (o[k] >= 0.f) ? o[k] : 0.01f * o[k];
        }
        float* dst = out + (size_t)node * 32 + lane * 8;
        *(float4*)(dst)     = make_float4(o[0], o[1], o[2], o[3]);
        *(float4*)(dst + 4) = make_float4(o[4], o[5], o[6], o[7]);
    }
}

// ---------------------------------------------------------------- launch
extern "C" void kernel_launch(void* const* d_in, const int* in_sizes, int n_in,
                              void* d_out, int out_size) {
    const float* x  = (const float*)d_in[0];
    const void*  ei = d_in[1];
    const float* W1 = (const float*)d_in[2];
    const float* b1 = (const float*)d_in[3];
    const float* W2 = (const float*)d_in[4];
    const float* b2 = (const float*)d_in[5];
    const float* W3 = (const float*)d_in[6];
    const float* b3 = (const float*)d_in[7];
    float* out = (float*)d_out;

    int N = in_sizes[0] / 64;
    int E = in_sizes[1] / 2;

    float* emb1 = out;
    float* emb2 = out + (size_t)N * 64;
    float* emb3 = out + (size_t)N * 128;

    int nblk = (N + SCAN_TILE - 1) / SCAN_TILE;
    int agg_blocks = (N * 32 + 255) / 256;

    // (1-3) CSR prefix; g_deg is zero on entry (bss / re-zeroed by prior call)
    k_count<<<(E + 255) / 256, 256>>>(ei, E, N);
    k_part<<<nblk, SCAN_TILE>>>(N);
    k_offs<<<nblk, SCAN_TILE>>>(N);
    // (4) gemm1 — ncu capture slot
    k_gemm<64, 64><<<(N + 63) / 64, 256>>>(x, W1, N);
    // (5) edge fill
    k_fill<<<(E + 255) / 256, 256>>>(ei, E, N);
    // (6-10) remaining pipeline
    k_agg64<true><<<agg_blocks, 256>>>(b1, emb1, N);
    k_gemm<64, 64><<<(N + 63) / 64, 256>>>(emb1, W2, N);
    k_agg64<true><<<agg_blocks, 256>>>(b2, emb2, N);
    k_gemm<64, 32><<<(N + 127) / 128, 256>>>(emb2, W3, N);
    k_agg32<false><<<agg_blocks, 256>>>(b3, emb3, N);
}

// round 6
// speedup vs baseline: 2.4711x; 1.2086x over previous
#include <cuda_runtime.h>
#include <cuda_fp16.h>

// ===========================================================================
// GCN: 3 layers, pull-based padded-CSR aggregation, no float atomics.
//   out_i = leakyrelu( dinv_i * ( sum_{e: dst=i} g[src_e] + g[i] ) + b )
//   with g = fp16( (h @ W) * dinv )  (row-scaled in GEMM epilogue)
//
// R2: multi-block scan. R4: fp16 gather table. R5: padded 4/8-edge agg.
// R6: GEMMs moved to tensor cores (mma.m16n8k16 f16->f32). The FFMA GEMM
//     was L1/LSU-bound at 35us; HMMA turns it into a pure streaming kernel.
// ===========================================================================

#define NMAX 100000
#define EMAX 1600000
#define PADMAX (EMAX + 8 * NMAX)
#define SCAN_TILE 1024
#define NBLK ((NMAX + SCAN_TILE - 1) / SCAN_TILE)   // 98

__device__ int    g_deg[NMAX];                   // .bss zero; re-zeroed by k_offs
__device__ float  g_dinv[NMAX];
__device__ int    g_offs[NMAX + 1];              // padded CSR offsets
__device__ int    g_cur[NMAX];
__device__ int    g_csrc[PADMAX];
__device__ int    g_bsum[NBLK];
__device__ __half g_Gh[(size_t)(NMAX + 1) * 64]; // +1: tail zero row (sentinel)

// per-warp dtype probe: int64 entries < 2^31 have zero high words; for int32
// data those words are random node ids -> 16 zeros is impossible.
__device__ __forceinline__ int probe_is64(const unsigned* w, int lane) {
    unsigned hw = w[2 * (lane & 15) + 1];
    return __ballot_sync(0xffffffffu, hw == 0u) == 0xffffffffu;
}

__device__ __forceinline__ int load_idx(const void* ei, size_t pos, int is64) {
    if (is64) return (int)((const long long*)ei)[pos];
    return ((const int*)ei)[pos];
}

// ---------------------------------------------------------------- CSR build
__global__ void k_count(const void* __restrict__ ei, int E, int N) {
    int lane = threadIdx.x & 31;
    int is64 = probe_is64((const unsigned*)ei, lane);
    int e = blockIdx.x * blockDim.x + threadIdx.x;
    if (e < E) {
        int dst = load_idx(ei, (size_t)E + e, is64);
        if ((unsigned)dst < (unsigned)N) atomicAdd(&g_deg[dst], 1);
    }
}

// per-block sums of PADDED degrees
__global__ void k_part(int N) {
    int i = blockIdx.x * SCAN_TILE + threadIdx.x;
    int d  = (i < N) ? g_deg[i] : 0;
    int pd = (d + 7) & ~7;
    int lane = threadIdx.x & 31, wid = threadIdx.x >> 5;
    #pragma unroll
    for (int o = 16; o > 0; o >>= 1) pd += __shfl_down_sync(0xffffffffu, pd, o);
    __shared__ int ws[32];
    if (lane == 0) ws[wid] = pd;
    __syncthreads();
    if (wid == 0) {
        int v = ws[lane];
        #pragma unroll
        for (int o = 16; o > 0; o >>= 1) v += __shfl_down_sync(0xffffffffu, v, o);
        if (lane == 0) g_bsum[blockIdx.x] = v;
    }
}

// fused: scan of block sums + block-wide scan of padded degrees ->
// offs/cur/dinv, sentinel pad fill, and re-zero g_deg for the next call.
__global__ void k_offs(int N) {
    __shared__ int sb[128];
    __shared__ int ws[32];
    int t = threadIdx.x;

    if (t < 128) {
        int v = (t < NBLK) ? g_bsum[t] : 0;
        int lane = t & 31, w = t >> 5;
        int s = v;
        #pragma unroll
        for (int o = 1; o < 32; o <<= 1) {
            int u = __shfl_up_sync(0xffffffffu, s, o);
            if (lane >= o) s += u;
        }
        if (lane == 31) ws[w] = s;
        sb[t] = s;
    }
    __syncthreads();
    if (t < 128) {
        int w = t >> 5;
        int add = 0;
        for (int q = 0; q < w; q++) add += ws[q];
        sb[t] += add;
    }
    __syncthreads();
    int blockpre = (blockIdx.x == 0) ? 0 : sb[blockIdx.x - 1];
    __syncthreads();  // ws reused below

    int i = blockIdx.x * SCAN_TILE + t;
    int d  = (i < N) ? g_deg[i] : 0;
    int pd = (d + 7) & ~7;
    int lane = t & 31, wid = t >> 5;
    int v = pd;
    #pragma unroll
    for (int o = 1; o < 32; o <<= 1) {
        int u = __shfl_up_sync(0xffffffffu, v, o);
        if (lane >= o) v += u;
    }
    if (lane == 31) ws[wid] = v;
    __syncthreads();
    if (wid == 0) {
        int w = ws[lane];
        #pragma unroll
        for (int o = 1; o < 32; o <<= 1) {
            int u = __shfl_up_sync(0xffffffffu, w, o);
            if (lane >= o) w += u;
        }
        ws[lane] = w;
    }
    __syncthreads();
    int incl = v + ((wid > 0) ? ws[wid - 1] : 0);
    int excl = incl - pd + blockpre;
    if (i < N) {
        g_offs[i] = excl;
        g_cur[i]  = excl;
        g_dinv[i] = rsqrtf((float)(d + 1));     // +1 self loop (real degree)
        for (int p = excl + d; p < excl + pd; p++) g_csrc[p] = NMAX;  // sentinel
        g_deg[i] = 0;                            // ready for next replay
        if (i == N - 1) g_offs[N] = excl + pd;
    }
}

__global__ void k_fill(const void* __restrict__ ei, int E, int N) {
    int lane = threadIdx.x & 31;
    int is64 = probe_is64((const unsigned*)ei, lane);
    int e = blockIdx.x * blockDim.x + threadIdx.x;
    if (e < E) {
        int dst = load_idx(ei, (size_t)E + e, is64);
        int src = load_idx(ei, (size_t)e, is64);
        if ((unsigned)dst < (unsigned)N) {
            int pos = atomicAdd(&g_cur[dst], 1);
            g_csrc[pos] = ((unsigned)src < (unsigned)N) ? src : 0;
        }
    }
}

// ---------------------------------------------------------------- HMMA GEMM
__device__ __forceinline__ void mma16816(float c[4], unsigned a0, unsigned a1,
                                         unsigned a2, unsigned a3,
                                         unsigned b0, unsigned b1) {
    asm volatile(
        "mma.sync.aligned.m16n8k16.row.col.f32.f16.f16.f32 "
        "{%0,%1,%2,%3}, {%4,%5,%6,%7}, {%8,%9}, {%0,%1,%2,%3};"
        : "+f"(c[0]), "+f"(c[1]), "+f"(c[2]), "+f"(c[3])
        : "r"(a0), "r"(a1), "r"(a2), "r"(a3), "r"(b0), "r"(b1));
}

// g_Gh = fp16( (X @ W) * dinv[row] ).  X:[N,64] fp32, W:[64,DOUT] fp32.
// Block: 128 threads / 4 warps, tile = 64 rows x DOUT cols, K=64.
// smem stride 72 halves -> fragment loads are provably bank-conflict-free.
template <int DOUT>
__global__ void k_hgemm(const float* __restrict__ X, const float* __restrict__ W, int N) {
    constexpr int S = 72;
    __shared__ __half sX[64 * S];
    __shared__ __half sWt[DOUT * S];   // transposed: sWt[n][k]

    int tid = threadIdx.x, lane = tid & 31, w = tid >> 5;
    int rowBase = blockIdx.x * 64;

    // W[k][n] -> sWt[n][k] (fp16), coalesced global read
    for (int idx = tid; idx < 64 * DOUT; idx += 128) {
        int k = idx / DOUT, n = idx % DOUT;
        sWt[n * S + k] = __float2half_rn(W[idx]);
    }
    // X tile fp32 -> fp16 smem, 8 float4 per thread, coalesced
    #pragma unroll
    for (int i = 0; i < 8; i++) {
        int idx = tid + i * 128;            // float4 index within 64x16
        int r = idx >> 4, c4 = idx & 15;
        int grow = rowBase + r;
        float4 v = (grow < N) ? *(const float4*)(X + (size_t)grow * 64 + c4 * 4)
                              : make_float4(0.f, 0.f, 0.f, 0.f);
        *(__half2*)&sX[r * S + c4 * 4]     = __floats2half2_rn(v.x, v.y);
        *(__half2*)&sX[r * S + c4 * 4 + 2] = __floats2half2_rn(v.z, v.w);
    }
    __syncthreads();

    constexpr int NT = DOUT / 8;
    float acc[NT][4];
    #pragma unroll
    for (int nt = 0; nt < NT; nt++)
        #pragma unroll
        for (int q = 0; q < 4; q++) acc[nt][q] = 0.f;

    int g = lane >> 2, tg = lane & 3;
    int r0 = w * 16 + g;

    #pragma unroll
    for (int kt = 0; kt < 4; kt++) {
        int k0 = kt * 16 + tg * 2;
        unsigned a0 = *(const unsigned*)&sX[r0 * S + k0];
        unsigned a1 = *(const unsigned*)&sX[(r0 + 8) * S + k0];
        unsigned a2 = *(const unsigned*)&sX[r0 * S + k0 + 8];
        unsigned a3 = *(const unsigned*)&sX[(r0 + 8) * S + k0 + 8];
        #pragma unroll
        for (int nt = 0; nt < NT; nt++) {
            int n = nt * 8 + g;
            unsigned b0 = *(const unsigned*)&sWt[n * S + k0];
            unsigned b1 = *(const unsigned*)&sWt[n * S + k0 + 8];
            mma16816(acc[nt], a0, a1, a2, a3, b0, b1);
        }
    }

    // epilogue: scale by dinv, convert, store half2
    int gr0 = rowBase + r0, gr1 = gr0 + 8;
    float s0 = (gr0 < N) ? g_dinv[gr0] : 0.f;
    float s1 = (gr1 < N) ? g_dinv[gr1] : 0.f;
    __half2* Gh2 = (__half2*)g_Gh;
    #pragma unroll
    for (int nt = 0; nt < NT; nt++) {
        int col = nt * 8 + tg * 2;
        if (gr0 < N)
            Gh2[((size_t)gr0 * DOUT + col) >> 1] =
                __floats2half2_rn(acc[nt][0] * s0, acc[nt][1] * s0);
        if (gr1 < N)
            Gh2[((size_t)gr1 * DOUT + col) >> 1] =
                __floats2half2_rn(acc[nt][2] * s1, acc[nt][3] * s1);
    }
}

// ---------------------------------------------------------------- aggregate
// D=64: warp-per-node, 4 edges/iter, LDG.128 gathers, fp32 accumulate.
template <bool RELU>
__global__ void k_agg64(const float* __restrict__ bias, float* __restrict__ out, int N) {
    int gid  = blockIdx.x * blockDim.x + threadIdx.x;
    int node = gid >> 5;
    int lane = gid & 31;
    if (node >= N) return;

    const uint4* __restrict__ G4 = (const uint4*)g_Gh;  // row = 8 granules
    int sub = lane & 7;
    int grp = lane >> 3;
    int beg = g_offs[node];
    int end = g_offs[node + 1];

    float acc[8];
    #pragma unroll
    for (int k = 0; k < 8; k++) acc[k] = 0.f;

    for (int e0 = beg; e0 < end; e0 += 32) {
        int idx = e0 + lane;
        int sl  = (idx < end) ? g_csrc[idx] : NMAX;
        int cnt = min(32, end - e0);          // multiple of 8
        for (int j = 0; j < cnt; j += 4) {
            int s = __shfl_sync(0xffffffffu, sl, j + grp);
            uint4 v = G4[(size_t)s * 8 + sub];
            const __half2* h = (const __half2*)&v;
            #pragma unroll
            for (int q = 0; q < 4; q++) {
                float2 f = __half22float2(h[q]);
                acc[2 * q]     += f.x;
                acc[2 * q + 1] += f.y;
            }
        }
    }
    #pragma unroll
    for (int k = 0; k < 8; k++) {
        acc[k] += __shfl_xor_sync(0xffffffffu, acc[k], 8);
        acc[k] += __shfl_xor_sync(0xffffffffu, acc[k], 16);
    }
    {
        uint4 v = G4[(size_t)node * 8 + sub];
        const __half2* h = (const __half2*)&v;
        #pragma unroll
        for (int q = 0; q < 4; q++) {
            float2 f = __half22float2(h[q]);
            acc[2 * q]     += f.x;
            acc[2 * q + 1] += f.y;
        }
    }
    if (lane < 8) {
        float sc = g_dinv[node];
        float o[8];
        #pragma unroll
        for (int k = 0; k < 8; k++) {
            o[k] = acc[k] * sc + bias[lane * 8 + k];
            if (RELU) o[k] = (o[k] >= 0.f) ? o[k] : 0.01f * o[k];
        }
        float* dst = out + (size_t)node * 64 + lane * 8;
        *(float4*)(dst)     = make_float4(o[0], o[1], o[2], o[3]);
        *(float4*)(dst + 4) = make_float4(o[4], o[5], o[6], o[7]);
    }
}

// D=32: warp-per-node, 8 edges/iter. Sentinel remapped to the zero tail row.
template <bool RELU>
__global__ void k_agg32(const float* __restrict__ bias, float* __restrict__ out, int N) {
    int gid  = blockIdx.x * blockDim.x + threadIdx.x;
    int node = gid >> 5;
    int lane = gid & 31;
    if (node >= N) return;

    const uint4* __restrict__ G4 = (const uint4*)g_Gh;  // row = 4 granules
    int sub = lane & 3;
    int grp = lane >> 2;
    int beg = g_offs[node];
    int end = g_offs[node + 1];

    float acc[8];
    #pragma unroll
    for (int k = 0; k < 8; k++) acc[k] = 0.f;

    for (int e0 = beg; e0 < end; e0 += 32) {
        int idx = e0 + lane;
        int sl  = (idx < end) ? g_csrc[idx] : NMAX;
        int cnt = min(32, end - e0);          // multiple of 8
        for (int j = 0; j < cnt; j += 8) {
            int s = __shfl_sync(0xffffffffu, sl, j + grp);
            size_t rb = (s == NMAX) ? ((size_t)NMAX * 8) : ((size_t)s * 4);
            uint4 v = G4[rb + sub];
            const __half2* h = (const __half2*)&v;
            #pragma unroll
            for (int q = 0; q < 4; q++) {
                float2 f = __half22float2(h[q]);
                acc[2 * q]     += f.x;
                acc[2 * q + 1] += f.y;
            }
        }
    }
    #pragma unroll
    for (int k = 0; k < 8; k++) {
        acc[k] += __shfl_xor_sync(0xffffffffu, acc[k], 4);
        acc[k] += __shfl_xor_sync(0xffffffffu, acc[k], 8);
        acc[k] += __shfl_xor_sync(0xffffffffu, acc[k], 16);
    }
    {
        uint4 v = G4[(size_t)node * 4 + sub];
        const __half2* h = (const __half2*)&v;
        #pragma unroll
        for (int q = 0; q < 4; q++) {
            float2 f = __half22float2(h[q]);
            acc[2 * q]     += f.x;
            acc[2 * q + 1] += f.y;
        }
    }
    if (lane < 4) {
        float sc = g_dinv[node];
        float o[8];
        #pragma unroll
        for (int k = 0; k < 8; k++) {
            o[k] = acc[k] * sc + bias[lane * 8 + k];
            if (RELU) o[k] = (o[k] >= 0.f) ? o[k] : 0.01f * o[k];
        }
        float* dst = out + (size_t)node * 32 + lane * 8;
        *(float4*)(dst)     = make_float4(o[0], o[1], o[2], o[3]);
        *(float4*)(dst + 4) = make_float4(o[4], o[5], o[6], o[7]);
    }
}

// ---------------------------------------------------------------- launch
extern "C" void kernel_launch(void* const* d_in, const int* in_sizes, int n_in,
                              void* d_out, int out_size) {
    const float* x  = (const float*)d_in[0];
    const void*  ei = d_in[1];
    const float* W1 = (const float*)d_in[2];
    const float* b1 = (const float*)d_in[3];
    const float* W2 = (const float*)d_in[4];
    const float* b2 = (const float*)d_in[5];
    const float* W3 = (const float*)d_in[6];
    const float* b3 = (const float*)d_in[7];
    float* out = (float*)d_out;

    int N = in_sizes[0] / 64;
    int E = in_sizes[1] / 2;

    float* emb1 = out;
    float* emb2 = out + (size_t)N * 64;
    float* emb3 = out + (size_t)N * 128;

    int nblk = (N + SCAN_TILE - 1) / SCAN_TILE;
    int gemm_blocks = (N + 63) / 64;
    int agg_blocks = (N * 32 + 255) / 256;

    k_count<<<(E + 255) / 256, 256>>>(ei, E, N);
    k_part<<<nblk, SCAN_TILE>>>(N);
    k_offs<<<nblk, SCAN_TILE>>>(N);
    // (4) gemm1 — ncu capture slot
    k_hgemm<64><<<gemm_blocks, 128>>>(x, W1, N);
    k_fill<<<(E + 255) / 256, 256>>>(ei, E, N);
    k_agg64<true><<<agg_blocks, 256>>>(b1, emb1, N);
    k_hgemm<64><<<gemm_blocks, 128>>>(emb1, W2, N);
    k_agg64<true><<<agg_blocks, 256>>>(b2, emb2, N);
    k_hgemm<32><<<gemm_blocks, 128>>>(emb2, W3, N);
    k_agg32<false><<<agg_blocks, 256>>>(b3, emb3, N);
}